// round 5
// baseline (speedup 1.0000x reference)
#include <cuda_runtime.h>
#include <stdint.h>

// BitInput: out[i] = (u_i < p[i>>8]) ? 1.0f : 0.0f
// u_i = jax.random.uniform(key(42)), threefry_partitionable:
//   (b0,b1) = threefry2x32_20(key=(0,42), x0=0, x1=i); bits = b0^b1
//   u = bitcast((bits>>9)|0x3f800000) - 1
// Compare as floats: uf = bitcast((bits>>9)|0x3f800000) = 1+u (exact),
// p1 = 1+p (exact: p is a multiple of 2^-23), uf < p1 <=> u < p.
//
// Pipe balancing, locally distributed: rotations 26 (x3), 29 (x2), 24 (x2),
// 16 (G4 only) computed via IMAD-pair rotate (fma pipe) so every round-group
// mixes alu and fma work; the rest stay on SHF (alu). k=8 conversions puts
// the alu floor (2*A) at the issue floor (T). Multipliers are runtime args
// so ptxas cannot strength-reduce them back to SHF.

#define KS1 42u
#define KS2 0x1BD11BF0u

static __device__ __forceinline__ uint32_t rotl32(uint32_t x, int r) {
    return __funnelshift_l(x, x, r);
}
// mul-based rotate: (x*m) | umulhi(x,m), m = 1<<r  (IMAD + IMAD.HI on fma pipe)
#define MR(x, m) ( ((x) * (m)) | __umulhi((x), (m)) )

static __device__ __forceinline__ float tf_bern(uint32_t i, float p1,
                                                uint32_t m26, uint32_t m29,
                                                uint32_t m16, uint32_t m24)
{
    uint32_t x1 = i + KS1;     // lo32(counter) + ks1
    uint32_t x0 = x1;          // round 1: x0 was 0, add is a copy

    // G1: 13,15,26,6  (26 on fma)
    x1 = rotl32(x1, 13) ^ x0;
    x0 += x1;  x1 = rotl32(x1, 15) ^ x0;
    x0 += x1;  x1 = MR(x1, m26) ^ x0;
    x0 += x1;  x1 = rotl32(x1,  6) ^ x0;
    x1 += KS2 + 1u;                      // inject (ks1 folded below, ks2+1)
    // G2: 17,29,16,24  (29,24 on fma)
    x0 = x0 + KS1 + x1;  x1 = rotl32(x1, 17) ^ x0;
    x0 += x1;  x1 = MR(x1, m29) ^ x0;
    x0 += x1;  x1 = rotl32(x1, 16) ^ x0;
    x0 += x1;  x1 = MR(x1, m24) ^ x0;
    x1 += 2u;                            // inject (ks2 folded, 2)
    // G3: 13,15,26,6  (26 on fma)
    x0 = x0 + KS2 + x1;  x1 = rotl32(x1, 13) ^ x0;
    x0 += x1;  x1 = rotl32(x1, 15) ^ x0;
    x0 += x1;  x1 = MR(x1, m26) ^ x0;
    x0 += x1;  x1 = rotl32(x1,  6) ^ x0;
    x1 += KS1 + 3u;                      // inject (0, ks1+3)
    // G4: 17,29,16,24  (29,16,24 on fma)
    x0 = x0 + x1;        x1 = rotl32(x1, 17) ^ x0;
    x0 += x1;  x1 = MR(x1, m29) ^ x0;
    x0 += x1;  x1 = MR(x1, m16) ^ x0;
    x0 += x1;  x1 = MR(x1, m24) ^ x0;
    x1 += KS2 + 4u;                      // inject (ks1 folded, ks2+4)
    // G5: 13,15,26,6  (26 on fma)
    x0 = x0 + KS1 + x1;  x1 = rotl32(x1, 13) ^ x0;
    x0 += x1;  x1 = rotl32(x1, 15) ^ x0;
    x0 += x1;  x1 = MR(x1, m26) ^ x0;
    x0 += x1;  x1 = rotl32(x1,  6) ^ x0;

    uint32_t bits = (x0 + KS2) ^ (x1 + 5u);   // final inject + fold
    // uf = (0x7F:bits) >> 9 = 0x3F800000 | (bits>>9) = 1 + u exactly
    float uf = __uint_as_float(__funnelshift_r(bits, 0x7Fu, 9));
    return (uf < p1) ? 1.0f : 0.0f;           // FSETP+FSEL on fma pipe
}

__global__ void __launch_bounds__(256)
bitinput_kernel(const float* __restrict__ prob, float4* __restrict__ out,
                uint32_t m26, uint32_t m29, uint32_t m16, uint32_t m24)
{
    const uint32_t t  = blockIdx.x * 256u + threadIdx.x;
    const uint32_t i0 = t << 3;                       // 8 consecutive elements
    // 8 consecutive elements share one p (p blocks span 256 elements)
    const float p1 = 1.0f + __ldg(&prob[i0 >> 8]);

    float4 v0, v1;
    v0.x = tf_bern(i0 + 0u, p1, m26, m29, m16, m24);
    v0.y = tf_bern(i0 + 1u, p1, m26, m29, m16, m24);
    v0.z = tf_bern(i0 + 2u, p1, m26, m29, m16, m24);
    v0.w = tf_bern(i0 + 3u, p1, m26, m29, m16, m24);
    v1.x = tf_bern(i0 + 4u, p1, m26, m29, m16, m24);
    v1.y = tf_bern(i0 + 5u, p1, m26, m29, m16, m24);
    v1.z = tf_bern(i0 + 6u, p1, m26, m29, m16, m24);
    v1.w = tf_bern(i0 + 7u, p1, m26, m29, m16, m24);

    __stcs(&out[2u * t], v0);
    __stcs(&out[2u * t + 1u], v1);
}

extern "C" void kernel_launch(void* const* d_in, const int* in_sizes, int n_in,
                              void* d_out, int out_size)
{
    const float* prob = (const float*)d_in[0];
    const uint32_t n      = (uint32_t)out_size;   // 134,217,728
    const uint32_t nthr   = n >> 3;               // 8 outputs per thread
    const uint32_t blocks = nthr / 256u;

    bitinput_kernel<<<blocks, 256>>>(prob, (float4*)d_out,
                                     1u << 26, 1u << 29, 1u << 16, 1u << 24);
}

// round 6
// speedup vs baseline: 1.6581x; 1.6581x over previous
#include <cuda_runtime.h>
#include <stdint.h>

// BitInput: out[i] = (u_i < p[i>>8]) ? 1.0f : 0.0f
// u_i = jax.random.uniform(key(42)), threefry_partitionable:
//   (b0,b1) = threefry2x32_20(key=(0,42), x0=0, x1=i); bits = b0^b1
//   u = (bits>>9) * 2^-23 exactly.  Integer compare: u < p <=> bits <u (p*2^23)<<9.
//
// Core identical to the proven R4 kernel (6 IMAD-pair rotations in G2/G4,
// folded key injections, free first round, int-domain threshold).
// Single change vs R4: 16 elements per thread to deepen chain interleave
// (more regs -> more independent threefry chains in flight).

#define KS1 42u
#define KS2 0x1BD11BF0u

static __device__ __forceinline__ uint32_t rotl32(uint32_t x, int r) {
    return __funnelshift_l(x, x, r);
}

// mul-based rotate: (x*m) | umulhi(x,m)  (m = 1<<r), IMAD + IMAD.HI on fma pipe
#define MROT(x, m) ( ((x) * (m)) | __umulhi((x), (m)) )

static __device__ __forceinline__ uint32_t tf_bits(uint32_t i, uint32_t m29,
                                                   uint32_t m16, uint32_t m24)
{
    uint32_t x1 = i + KS1;     // lo32(counter) + ks1
    uint32_t x0 = x1;          // round-1 add with x0=0 is a copy

    // group 1: rotations 13,15,26,6
    x1 = rotl32(x1, 13) ^ x0;
    x0 += x1;  x1 = rotl32(x1, 15) ^ x0;
    x0 += x1;  x1 = rotl32(x1, 26) ^ x0;
    x0 += x1;  x1 = rotl32(x1,  6) ^ x0;
    // inject (ks1, ks2+1): x0 part folded into next round's IADD3
    x1 += KS2 + 1u;
    // group 2: rotations 17,29,16,24
    x0 = x0 + KS1 + x1;  x1 = rotl32(x1, 17) ^ x0;
    x0 += x1;  x1 = (MROT(x1, m29)) ^ x0;
    x0 += x1;  x1 = (MROT(x1, m16)) ^ x0;
    x0 += x1;  x1 = (MROT(x1, m24)) ^ x0;
    // inject (ks2, 2)
    x1 += 2u;
    // group 3: 13,15,26,6
    x0 = x0 + KS2 + x1;  x1 = rotl32(x1, 13) ^ x0;
    x0 += x1;  x1 = rotl32(x1, 15) ^ x0;
    x0 += x1;  x1 = rotl32(x1, 26) ^ x0;
    x0 += x1;  x1 = rotl32(x1,  6) ^ x0;
    // inject (0, ks1+3): x0 injection is zero
    x1 += KS1 + 3u;
    // group 4: 17,29,16,24
    x0 = x0 + x1;        x1 = rotl32(x1, 17) ^ x0;
    x0 += x1;  x1 = (MROT(x1, m29)) ^ x0;
    x0 += x1;  x1 = (MROT(x1, m16)) ^ x0;
    x0 += x1;  x1 = (MROT(x1, m24)) ^ x0;
    // inject (ks1, ks2+4)
    x1 += KS2 + 4u;
    // group 5: 13,15,26,6
    x0 = x0 + KS1 + x1;  x1 = rotl32(x1, 13) ^ x0;
    x0 += x1;  x1 = rotl32(x1, 15) ^ x0;
    x0 += x1;  x1 = rotl32(x1, 26) ^ x0;
    x0 += x1;  x1 = rotl32(x1,  6) ^ x0;
    // final inject (ks2, 5) + partitionable fold
    return (x0 + KS2) ^ (x1 + 5u);
}

__global__ void __launch_bounds__(256)
bitinput_kernel(const float* __restrict__ prob, uint4* __restrict__ out,
                uint32_t m29, uint32_t m16, uint32_t m24)
{
    const uint32_t t  = blockIdx.x * 256u + threadIdx.x;
    const uint32_t i0 = t << 4;                       // 16 consecutive elements
    // 16 consecutive elements share one p (p blocks span 256 elements)
    const float p = __ldg(&prob[i0 >> 8]);
    // p = m * 2^-23 exactly -> thr = m << 9; bits <u thr  <=>  u < p
    const uint32_t thr = ((uint32_t)(p * 8388608.0f)) << 9;

#pragma unroll
    for (int h = 0; h < 4; ++h) {
        uint32_t r[4];
#pragma unroll
        for (int j = 0; j < 4; ++j)
            r[j] = tf_bits(i0 + (uint32_t)(4 * h + j), m29, m16, m24);
        uint4 v;
        v.x = (r[0] < thr) ? 0x3f800000u : 0u;
        v.y = (r[1] < thr) ? 0x3f800000u : 0u;
        v.z = (r[2] < thr) ? 0x3f800000u : 0u;
        v.w = (r[3] < thr) ? 0x3f800000u : 0u;
        __stcs(&out[4u * t + (uint32_t)h], v);
    }
}

extern "C" void kernel_launch(void* const* d_in, const int* in_sizes, int n_in,
                              void* d_out, int out_size)
{
    const float* prob = (const float*)d_in[0];
    const uint32_t n      = (uint32_t)out_size;   // 134,217,728
    const uint32_t nthr   = n >> 4;               // 16 outputs per thread
    const uint32_t blocks = nthr / 256u;

    bitinput_kernel<<<blocks, 256>>>(prob, (uint4*)d_out,
                                     1u << 29, 1u << 16, 1u << 24);
}